// round 16
// baseline (speedup 1.0000x reference)
#include <cuda_runtime.h>
#include <math.h>

#define L_LAYERS 32
#define BEAM 8
#define KV2 2
#define HEADS 8
#define SEQ 1024
#define HDIM 64
#define VOCAB 50257
#define HIST 128
#define TOPK 8
#define CHUNKS 32
#define CHUNK_SZ 1572          // 4*393; 32*1572 = 50304 >= 50257
#define CHUNK_F4 393
#define K1_THREADS 256
#define K1_BLOCKS (BEAM * CHUNKS)   // 256

// per-(l,b) slab: KV2*HEADS*SEQ*HDIM floats = 1,048,576 floats = 262,144 float4
#define SLAB_F4 262144
#define GRPS_PER_LAYER 256     // 262144 f4 / 1024 f4 per block
#define CHUNK_GLOBAL (L_LAYERS * GRPS_PER_LAYER)   // 8192

// output offsets (float32 elements, concatenated in reference return order)
#define OFF_KV   0LL
#define OFF_SAVE 268435456LL
#define OFF_PROB 268436488LL
#define OFF_TBI  268436496LL
#define OFF_MAX  268436504LL

// device-global scratch (no allocations allowed)
__device__ float g_part_m[BEAM * CHUNKS];
__device__ float g_part_s[BEAM * CHUNKS];
__device__ float g_part_val[BEAM * CHUNKS * TOPK];
__device__ int   g_part_idx[BEAM * CHUNKS * TOPK];
__device__ int   g_beam_index[BEAM];
__device__ int   g_dst_mask[BEAM];
__device__ unsigned int g_done = 0;   // self-resetting completion counter

__device__ __forceinline__ bool cand_gt(float av, int ai, float bv, int bi) {
    // strictly greater value wins; on exact tie, lower index wins (jax.lax.top_k order)
    return (av > bv) || (av == bv && ai < bi);
}

// ---------------------------------------------------------------------------
// Fused kernel: per-chunk softmax partials + top-8 (float4-vectorized, batch
// loads -> max tree -> independent exps); LAST block merges (warp-per-row),
// does global beam selection, writes small outputs.
// grid = 256 blocks x 256 threads.
// ---------------------------------------------------------------------------
__global__ void __launch_bounds__(K1_THREADS)
topk_select_kernel(const float* __restrict__ logits,
                   const int* __restrict__ save_id,
                   const float* __restrict__ prev_prob,
                   float* __restrict__ out) {
    const int chunk = blockIdx.x & (CHUNKS - 1);
    const int r     = blockIdx.x >> 5;
    const int tid   = threadIdx.x;
    const long long row_f4 = ((long long)r * VOCAB) >> 2;   // VOCAB not /4; handle via element math
    // row base in floats (VOCAB per row, not multiple of 4). We index float4
    // against a per-row float4 view only when the row base is 16B aligned:
    // r*VOCAB elements * 4B — alignment varies per row, so use element loads
    // through float4 on a byte-offset basis instead:
    const float* row = logits + (long long)r * VOCAB;

    // 2 predicated float4-equivalent batches of 4 scalars each, fully unrolled.
    // (row base may be unaligned for odd r, so issue 8 independent scalar
    // __ldcs loads — still batched, no serial dependence.)
    const int start = chunk * CHUNK_SZ;
    float v[8];
    int   vi[8];
#pragma unroll
    for (int j = 0; j < 8; j++) {
        int i = start + tid + j * K1_THREADS;
        bool ok = (i < min(start + CHUNK_SZ, VOCAB));
        v[j]  = ok ? __ldcs(row + i) : -INFINITY;
        vi[j] = ok ? i : 0x7fffffff;
    }
    (void)row_f4;

    // max tree (3 levels, independent)
    float m01 = fmaxf(v[0], v[1]), m23 = fmaxf(v[2], v[3]);
    float m45 = fmaxf(v[4], v[5]), m67 = fmaxf(v[6], v[7]);
    float m03 = fmaxf(m01, m23),   m47 = fmaxf(m45, m67);
    float m = fmaxf(m03, m47);

    // independent exps, add tree
    float s = 0.0f;
    if (m > -INFINITY) {
        float e0 = (v[0] > -INFINITY) ? __expf(v[0] - m) : 0.0f;
        float e1 = (v[1] > -INFINITY) ? __expf(v[1] - m) : 0.0f;
        float e2 = (v[2] > -INFINITY) ? __expf(v[2] - m) : 0.0f;
        float e3 = (v[3] > -INFINITY) ? __expf(v[3] - m) : 0.0f;
        float e4 = (v[4] > -INFINITY) ? __expf(v[4] - m) : 0.0f;
        float e5 = (v[5] > -INFINITY) ? __expf(v[5] - m) : 0.0f;
        float e6 = (v[6] > -INFINITY) ? __expf(v[6] - m) : 0.0f;
        float e7 = (v[7] > -INFINITY) ? __expf(v[7] - m) : 0.0f;
        s = ((e0 + e1) + (e2 + e3)) + ((e4 + e5) + (e6 + e7));
    }

    // local sorted top-8 from the 8 registers
    float lv[TOPK];
    int   li[TOPK];
#pragma unroll
    for (int k = 0; k < TOPK; k++) { lv[k] = -INFINITY; li[k] = 0x7fffffff; }
#pragma unroll
    for (int j = 0; j < 8; j++) {
        if (cand_gt(v[j], vi[j], lv[TOPK - 1], li[TOPK - 1])) {
            int k = TOPK - 1;
            while (k > 0 && cand_gt(v[j], vi[j], lv[k - 1], li[k - 1])) {
                lv[k] = lv[k - 1]; li[k] = li[k - 1]; k--;
            }
            lv[k] = v[j]; li[k] = vi[j];
        }
    }

    __shared__ float sm[K1_THREADS], ss[K1_THREADS];
    sm[tid] = m; ss[tid] = s;
    __syncthreads();
    for (int st = K1_THREADS / 2; st > 0; st >>= 1) {
        if (tid < st) {
            float m1 = sm[tid], s1 = ss[tid];
            float m2 = sm[tid + st], s2 = ss[tid + st];
            float M = fmaxf(m1, m2);
            float S = ((m1 > -INFINITY) ? s1 * __expf(m1 - M) : 0.0f)
                    + ((m2 > -INFINITY) ? s2 * __expf(m2 - M) : 0.0f);
            sm[tid] = M; ss[tid] = S;
        }
        __syncthreads();
    }

    __shared__ float sv[K1_THREADS * TOPK];
    __shared__ int   si[K1_THREADS * TOPK];
#pragma unroll
    for (int k = 0; k < TOPK; k++) { sv[tid * TOPK + k] = lv[k]; si[tid * TOPK + k] = li[k]; }
    __syncthreads();

    for (int step = 1; step < K1_THREADS; step <<= 1) {
        if ((tid & (2 * step - 1)) == 0) {
            float* A  = &sv[tid * TOPK];
            int*   Ai = &si[tid * TOPK];
            float* B  = &sv[(tid + step) * TOPK];
            int*   Bi = &si[(tid + step) * TOPK];
            float mv[TOPK]; int mi[TOPK];
            int pa = 0, pb = 0;
#pragma unroll
            for (int k = 0; k < TOPK; k++) {
                if (cand_gt(A[pa], Ai[pa], B[pb], Bi[pb])) { mv[k] = A[pa]; mi[k] = Ai[pa]; pa++; }
                else                                        { mv[k] = B[pb]; mi[k] = Bi[pb]; pb++; }
            }
#pragma unroll
            for (int k = 0; k < TOPK; k++) { A[k] = mv[k]; Ai[k] = mi[k]; }
        }
        __syncthreads();
    }

    if (tid == 0) {
        g_part_m[blockIdx.x] = sm[0];
        g_part_s[blockIdx.x] = ss[0];
    }
    if (tid < TOPK) {
        g_part_val[blockIdx.x * TOPK + tid] = sv[tid];
        g_part_idx[blockIdx.x * TOPK + tid] = si[tid];
    }

    // -------- last-block merge --------
    __shared__ bool is_last;
    __threadfence();
    if (tid == 0) {
        unsigned int prev = atomicAdd(&g_done, 1u);
        is_last = (prev == (unsigned)(K1_BLOCKS - 1));
    }
    __syncthreads();
    if (!is_last) return;
    __threadfence();   // acquire side

    __shared__ float cv[BEAM * TOPK];
    __shared__ int   ci[BEAM * TOPK];
    __shared__ int   s_beam[BEAM];
    __shared__ int   s_tbi[BEAM];
    __shared__ float s_prob[BEAM];

    const int wid  = tid >> 5;
    const int lane = tid & 31;

    if (wid < BEAM) {
        const int rr = wid;
        float M = g_part_m[rr * CHUNKS + lane];
        float S = g_part_s[rr * CHUNKS + lane];
#pragma unroll
        for (int o = 16; o > 0; o >>= 1) {
            float M2 = __shfl_down_sync(0xffffffffu, M, o);
            float S2 = __shfl_down_sync(0xffffffffu, S, o);
            float Mn = fmaxf(M, M2);
            float Sn = ((M  > -INFINITY) ? S  * __expf(M  - Mn) : 0.0f)
                     + ((M2 > -INFINITY) ? S2 * __expf(M2 - Mn) : 0.0f);
            M = Mn; S = Sn;
        }
        float lse = M + logf(S);
        lse = __shfl_sync(0xffffffffu, lse, 0);
        const float pprev = prev_prob[rr];

        float qv[8];
        int   qi[8];
        bool  used[8];
#pragma unroll
        for (int j = 0; j < 8; j++) {
            int idx = rr * (CHUNKS * TOPK) + lane + 32 * j;
            qv[j] = g_part_val[idx];
            qi[j] = g_part_idx[idx];
            used[j] = false;
        }

        for (int k = 0; k < TOPK; k++) {
            float bv = -INFINITY; int bidx = 0x7fffffff; int bj = -1;
#pragma unroll
            for (int j = 0; j < 8; j++) {
                if (!used[j] && cand_gt(qv[j], qi[j], bv, bidx)) {
                    bv = qv[j]; bidx = qi[j]; bj = j;
                }
            }
            int bl = lane;
#pragma unroll
            for (int o = 16; o > 0; o >>= 1) {
                float ov = __shfl_down_sync(0xffffffffu, bv, o);
                int   oi = __shfl_down_sync(0xffffffffu, bidx, o);
                int   ol = __shfl_down_sync(0xffffffffu, bl, o);
                int   oj = __shfl_down_sync(0xffffffffu, bj, o);
                if (cand_gt(ov, oi, bv, bidx)) { bv = ov; bidx = oi; bl = ol; bj = oj; }
            }
            bv   = __shfl_sync(0xffffffffu, bv, 0);
            bidx = __shfl_sync(0xffffffffu, bidx, 0);
            bl   = __shfl_sync(0xffffffffu, bl, 0);
            bj   = __shfl_sync(0xffffffffu, bj, 0);
            if (lane == bl) used[bj] = true;
            if (lane == 0) {
                cv[rr * TOPK + k] = bv - lse + pprev;
                ci[rr * TOPK + k] = bidx;
            }
        }
    }
    __syncthreads();

    if (tid == 0) {
        bool usedc[BEAM * TOPK];
        for (int i = 0; i < BEAM * TOPK; i++) usedc[i] = false;
        for (int b = 0; b < BEAM; b++) {
            int best = -1;
            for (int i = 0; i < BEAM * TOPK; i++) {
                if (usedc[i]) continue;
                if (best < 0 || cv[i] > cv[best]) best = i;  // strict > keeps lower flat index
            }
            usedc[best] = true;
            s_beam[b] = best >> 3;
            s_tbi[b]  = ci[best];
            s_prob[b] = cv[best];
            g_beam_index[b] = best >> 3;
        }
        for (int u = 0; u < BEAM; u++) {
            int mask = 0;
            bool canonical = true;
            for (int p = 0; p < u; p++)
                if (s_beam[p] == s_beam[u]) { canonical = false; break; }
            if (canonical)
                for (int b = u; b < BEAM; b++)
                    if (s_beam[b] == s_beam[u]) mask |= (1 << b);
            g_dst_mask[u] = mask;
        }
    }
    __syncthreads();

    for (int i = tid; i < BEAM * (HIST + 1); i += blockDim.x) {
        int b = i / (HIST + 1);
        int c = i % (HIST + 1);
        int val = (c < HIST) ? save_id[s_beam[b] * HIST + c] : s_tbi[b];
        out[OFF_SAVE + i] = (float)val;
    }
    if (tid < BEAM) {
        out[OFF_PROB + tid] = s_prob[tid];
        out[OFF_TBI + tid]  = (float)s_tbi[tid];
    }
    if (tid == 0) out[OFF_MAX] = (float)s_tbi[0];

    __syncthreads();
    if (tid == 0) g_done = 0;   // reset for next graph replay
}

// ---------------------------------------------------------------------------
// Gather: measured-best structure (65536 blocks, MLP=4, __ldcs/__stcs).
// Per-block smem broadcast + BAR removed: threads read the two 4B globals
// directly (L1-resident after first touch).
// ---------------------------------------------------------------------------
__global__ void __launch_bounds__(256) gather_kernel(const float4* __restrict__ kv,
                                                     float4* __restrict__ out) {
    const int u    = blockIdx.x & 7;
    const int mask = g_dst_mask[u];
    if (mask == 0) return;                       // duplicate slot: no work
    const int sb   = g_beam_index[u];

    const int chunk_global = blockIdx.x >> 3;
    const int grp          = chunk_global & (GRPS_PER_LAYER - 1);
    const int l            = chunk_global >> 8;

    const long long lbase = (long long)l * BEAM * SLAB_F4;
    const int off = grp * 1024 + threadIdx.x;

    const float4* src = kv + (lbase + (long long)sb * SLAB_F4 + off);
    float4 v0 = __ldcs(src + 0);
    float4 v1 = __ldcs(src + 256);
    float4 v2 = __ldcs(src + 512);
    float4 v3 = __ldcs(src + 768);

#pragma unroll
    for (int b = 0; b < BEAM; b++) {
        if (mask & (1 << b)) {
            float4* dst = out + (lbase + (long long)b * SLAB_F4 + off);
            __stcs(dst + 0,   v0);
            __stcs(dst + 256, v1);
            __stcs(dst + 512, v2);
            __stcs(dst + 768, v3);
        }
    }
}

// ---------------------------------------------------------------------------
extern "C" void kernel_launch(void* const* d_in, const int* in_sizes, int n_in,
                              void* d_out, int out_size) {
    const float* kv_cache  = (const float*)d_in[0];
    const float* logits    = (const float*)d_in[1];
    const int*   save_id   = (const int*)d_in[2];
    const float* prev_prob = (const float*)d_in[3];
    float* out = (float*)d_out;

    topk_select_kernel<<<K1_BLOCKS, K1_THREADS>>>(logits, save_id, prev_prob, out);
    gather_kernel<<<CHUNK_GLOBAL * BEAM, 256>>>(
        (const float4*)kv_cache, (float4*)(out + OFF_KV));
}